// round 2
// baseline (speedup 1.0000x reference)
#include <cuda_runtime.h>
#include <cuda_bf16.h>

#define N_COLS 4096
#define THREADS 1024
#define HALF_T 512

__device__ float g_row_sums[8192];  // enough for B up to 8192

__global__ __launch_bounds__(THREADS, 2)
void w1_row_kernel(const float* __restrict__ pred,
                   const float* __restrict__ tru)
{
    __shared__ float s[2][N_COLS];

    const int row  = blockIdx.x;
    const int half = threadIdx.x >> 9;      // 0 -> pred, 1 -> true
    const int t    = threadIdx.x & (HALF_T - 1);

    const float* __restrict__ src = half ? tru : pred;
    float* buf = s[half];

    // Load row into shared
    #pragma unroll
    for (int i = t; i < N_COLS; i += HALF_T) {
        buf[i] = src[(size_t)row * N_COLS + i];
    }
    __syncthreads();

    // Bitonic sort, ascending (n = 4096 -> 78 stages)
    for (int k = 2; k <= N_COLS; k <<= 1) {
        for (int j = k >> 1; j > 0; j >>= 1) {
            #pragma unroll
            for (int i = t; i < N_COLS; i += HALF_T) {
                int ixj = i ^ j;
                if (ixj > i) {
                    float a = buf[i];
                    float b = buf[ixj];
                    bool up = ((i & k) == 0);
                    if ((a > b) == up) {
                        buf[i]   = b;
                        buf[ixj] = a;
                    }
                }
            }
            __syncthreads();
        }
    }

    // Sum |pred_sorted - true_sorted| over the row
    float local = 0.0f;
    for (int i = threadIdx.x; i < N_COLS; i += THREADS) {
        local += fabsf(s[0][i] - s[1][i]);
    }

    // Block reduction (warp shuffle + smem)
    __shared__ float red[32];
    #pragma unroll
    for (int o = 16; o > 0; o >>= 1)
        local += __shfl_down_sync(0xffffffffu, local, o);
    if ((threadIdx.x & 31) == 0) red[threadIdx.x >> 5] = local;
    __syncthreads();
    if (threadIdx.x < 32) {
        float v = red[threadIdx.x];
        #pragma unroll
        for (int o = 16; o > 0; o >>= 1)
            v += __shfl_down_sync(0xffffffffu, v, o);
        if (threadIdx.x == 0) g_row_sums[row] = v;
    }
}

// Deterministic final reduction: single block, fixed iteration order.
__global__ void w1_reduce_kernel(float* __restrict__ out, int B)
{
    __shared__ float red[32];
    float local = 0.0f;
    for (int i = threadIdx.x; i < B; i += 1024)
        local += g_row_sums[i];
    #pragma unroll
    for (int o = 16; o > 0; o >>= 1)
        local += __shfl_down_sync(0xffffffffu, local, o);
    if ((threadIdx.x & 31) == 0) red[threadIdx.x >> 5] = local;
    __syncthreads();
    if (threadIdx.x < 32) {
        float v = red[threadIdx.x];
        #pragma unroll
        for (int o = 16; o > 0; o >>= 1)
            v += __shfl_down_sync(0xffffffffu, v, o);
        if (threadIdx.x == 0)
            out[0] = v / ((float)N_COLS * (float)B);
    }
}

extern "C" void kernel_launch(void* const* d_in, const int* in_sizes, int n_in,
                              void* d_out, int out_size)
{
    const float* pred = (const float*)d_in[0];
    const float* tru  = (const float*)d_in[1];
    float* out = (float*)d_out;

    const int B = in_sizes[0] / N_COLS;  // 4096

    w1_row_kernel<<<B, THREADS>>>(pred, tru);
    w1_reduce_kernel<<<1, 1024>>>(out, B);
}

// round 3
// speedup vs baseline: 3.2468x; 3.2468x over previous
#include <cuda_runtime.h>
#include <cuda_bf16.h>

#define N_COLS 4096
#define NT     512          // threads per row-CTA; 8 elements/thread/array

__device__ float g_row_sums[8192];

static __device__ __forceinline__ void ce(float& x, float& y, bool up) {
    float lo = fminf(x, y);
    float hi = fmaxf(x, y);
    x = up ? lo : hi;
    y = up ? hi : lo;
}

// Bitonic stages k=2,4,8 on the 8 register-resident elements (global idx t*8+e).
static __device__ __forceinline__ void sort8(float r[8], bool up8) {
    // k=2
    ce(r[0], r[1], true );  ce(r[2], r[3], false);
    ce(r[4], r[5], true );  ce(r[6], r[7], false);
    // k=4, j=2
    ce(r[0], r[2], true );  ce(r[1], r[3], true );
    ce(r[4], r[6], false);  ce(r[5], r[7], false);
    // k=4, j=1
    ce(r[0], r[1], true );  ce(r[2], r[3], true );
    ce(r[4], r[5], false);  ce(r[6], r[7], false);
    // k=8, j=4,2,1 (uniform direction up8)
    ce(r[0], r[4], up8); ce(r[1], r[5], up8); ce(r[2], r[6], up8); ce(r[3], r[7], up8);
    ce(r[0], r[2], up8); ce(r[1], r[3], up8); ce(r[4], r[6], up8); ce(r[5], r[7], up8);
    ce(r[0], r[1], up8); ce(r[2], r[3], up8); ce(r[4], r[5], up8); ce(r[6], r[7], up8);
}

// Bitonic merge j=4,2,1 inside the 8 registers, uniform direction.
static __device__ __forceinline__ void local_merge8(float r[8], bool up) {
    ce(r[0], r[4], up); ce(r[1], r[5], up); ce(r[2], r[6], up); ce(r[3], r[7], up);
    ce(r[0], r[2], up); ce(r[1], r[3], up); ce(r[4], r[6], up); ce(r[5], r[7], up);
    ce(r[0], r[1], up); ce(r[2], r[3], up); ce(r[4], r[5], up); ce(r[6], r[7], up);
}

// Cross-thread stage via warp shuffle: partner = lane ^ m (m <= 16).
static __device__ __forceinline__ void shfl_stage(float r[8], int m, bool keep_min) {
    #pragma unroll
    for (int e = 0; e < 8; e++) {
        float o = __shfl_xor_sync(0xffffffffu, r[e], m);
        r[e] = keep_min ? fminf(r[e], o) : fmaxf(r[e], o);
    }
}

__global__ __launch_bounds__(NT, 2)
void w1_row_kernel(const float4* __restrict__ pred,
                   const float4* __restrict__ tru)
{
    __shared__ float s[2][8][NT];   // [array][reg][thread], conflict-free layout

    const int row = blockIdx.x;
    const int t   = threadIdx.x;

    float a[8], b[8];

    // Load: thread t owns global elements [t*8, t*8+8) of both rows. 2x float4 each.
    {
        const size_t base = (size_t)row * (N_COLS / 4) + t * 2;
        float4 p0 = pred[base], p1 = pred[base + 1];
        float4 q0 = tru[base],  q1 = tru[base + 1];
        a[0]=p0.x; a[1]=p0.y; a[2]=p0.z; a[3]=p0.w;
        a[4]=p1.x; a[5]=p1.y; a[6]=p1.z; a[7]=p1.w;
        b[0]=q0.x; b[1]=q0.y; b[2]=q0.z; b[3]=q0.w;
        b[4]=q1.x; b[5]=q1.y; b[6]=q1.z; b[7]=q1.w;
    }

    // Stages k=2..8: fully in registers.
    const bool up8 = ((t & 1) == 0);
    sort8(a, up8);
    sort8(b, up8);

    // Stages k=16..4096.
    #pragma unroll
    for (int k = 16; k <= N_COLS; k <<= 1) {
        const bool up = (((t << 3) & k) == 0);

        // Cross-thread strides j >= 256: partner thread t^m, m >= 32 -> smem.
        #pragma unroll
        for (int j = k >> 1; j >= 256; j >>= 1) {
            const int  m        = j >> 3;
            const bool keep_min = (((t & m) == 0) == up);
            #pragma unroll
            for (int e = 0; e < 8; e++) { s[0][e][t] = a[e]; s[1][e][t] = b[e]; }
            __syncthreads();
            const int pt = t ^ m;
            #pragma unroll
            for (int e = 0; e < 8; e++) {
                float oa = s[0][e][pt];
                float ob = s[1][e][pt];
                a[e] = keep_min ? fminf(a[e], oa) : fmaxf(a[e], oa);
                b[e] = keep_min ? fminf(b[e], ob) : fmaxf(b[e], ob);
            }
            __syncthreads();
        }

        // Cross-thread strides 8..128: warp shuffles (m = 1..16).
        {
            const int jstart = (k >> 1) > 128 ? 128 : (k >> 1);
            #pragma unroll
            for (int j = jstart; j >= 8; j >>= 1) {
                const int  m        = j >> 3;
                const bool keep_min = (((t & m) == 0) == up);
                shfl_stage(a, m, keep_min);
                shfl_stage(b, m, keep_min);
            }
        }

        // Strides 4,2,1: in registers.
        local_merge8(a, up);
        local_merge8(b, up);
    }

    // Both sorted ascending; matching quantile positions live in the same thread.
    float local = 0.0f;
    #pragma unroll
    for (int e = 0; e < 8; e++) local += fabsf(a[e] - b[e]);

    // Block reduction (16 warps).
    __shared__ float red[16];
    #pragma unroll
    for (int o = 16; o > 0; o >>= 1)
        local += __shfl_down_sync(0xffffffffu, local, o);
    if ((t & 31) == 0) red[t >> 5] = local;
    __syncthreads();
    if (t < 32) {
        float v = (t < 16) ? red[t] : 0.0f;
        #pragma unroll
        for (int o = 8; o > 0; o >>= 1)
            v += __shfl_down_sync(0xffffffffu, v, o);
        if (t == 0) g_row_sums[row] = v;
    }
}

// Deterministic final reduction: single block, fixed iteration order.
__global__ void w1_reduce_kernel(float* __restrict__ out, int B)
{
    __shared__ float red[32];
    float local = 0.0f;
    for (int i = threadIdx.x; i < B; i += 1024)
        local += g_row_sums[i];
    #pragma unroll
    for (int o = 16; o > 0; o >>= 1)
        local += __shfl_down_sync(0xffffffffu, local, o);
    if ((threadIdx.x & 31) == 0) red[threadIdx.x >> 5] = local;
    __syncthreads();
    if (threadIdx.x < 32) {
        float v = red[threadIdx.x];
        #pragma unroll
        for (int o = 16; o > 0; o >>= 1)
            v += __shfl_down_sync(0xffffffffu, v, o);
        if (threadIdx.x == 0)
            out[0] = v / ((float)N_COLS * (float)B);
    }
}

extern "C" void kernel_launch(void* const* d_in, const int* in_sizes, int n_in,
                              void* d_out, int out_size)
{
    const float4* pred = (const float4*)d_in[0];
    const float4* tru  = (const float4*)d_in[1];
    float* out = (float*)d_out;

    const int B = in_sizes[0] / N_COLS;  // 4096

    w1_row_kernel<<<B, NT>>>(pred, tru);
    w1_reduce_kernel<<<1, 1024>>>(out, B);
}

// round 4
// speedup vs baseline: 3.6767x; 1.1324x over previous
#include <cuda_runtime.h>
#include <cuda_bf16.h>

#define N_COLS 4096
#define NT     512          // threads per row-CTA; 8 elements/thread/array

__device__ float g_row_sums[8192];

// min/max overloads: float -> FMNMX (fma pipe), int -> IMNMX (alu pipe).
// All inputs are non-negative floats, so int bit-pattern order == float order.
static __device__ __forceinline__ float mn(float x, float y) { return fminf(x, y); }
static __device__ __forceinline__ float mx(float x, float y) { return fmaxf(x, y); }
static __device__ __forceinline__ int   mn(int x, int y)     { return ::min(x, y); }
static __device__ __forceinline__ int   mx(int x, int y)     { return ::max(x, y); }

template <typename T>
static __device__ __forceinline__ void ce(T& x, T& y, bool up) {
    T lo = mn(x, y);
    T hi = mx(x, y);
    x = up ? lo : hi;
    y = up ? hi : lo;
}
// ascending compare-exchange
template <typename T>
static __device__ __forceinline__ void cea(T& x, T& y) {
    T lo = mn(x, y);
    y = mx(x, y);
    x = lo;
}

// Bitonic stages k=2,4,8 on 8 register-resident elements (global idx t*8+e).
template <typename T>
static __device__ __forceinline__ void sort8(T r[8], bool up8) {
    ce(r[0], r[1], true );  ce(r[2], r[3], false);
    ce(r[4], r[5], true );  ce(r[6], r[7], false);
    ce(r[0], r[2], true );  ce(r[1], r[3], true );
    ce(r[4], r[6], false);  ce(r[5], r[7], false);
    ce(r[0], r[1], true );  ce(r[2], r[3], true );
    ce(r[4], r[5], false);  ce(r[6], r[7], false);
    ce(r[0], r[4], up8); ce(r[1], r[5], up8); ce(r[2], r[6], up8); ce(r[3], r[7], up8);
    ce(r[0], r[2], up8); ce(r[1], r[3], up8); ce(r[4], r[6], up8); ce(r[5], r[7], up8);
    ce(r[0], r[1], up8); ce(r[2], r[3], up8); ce(r[4], r[5], up8); ce(r[6], r[7], up8);
}

template <typename T>
static __device__ __forceinline__ void local_merge8(T r[8], bool up) {
    ce(r[0], r[4], up); ce(r[1], r[5], up); ce(r[2], r[6], up); ce(r[3], r[7], up);
    ce(r[0], r[2], up); ce(r[1], r[3], up); ce(r[4], r[6], up); ce(r[5], r[7], up);
    ce(r[0], r[1], up); ce(r[2], r[3], up); ce(r[4], r[5], up); ce(r[6], r[7], up);
}

template <typename T>
static __device__ __forceinline__ void shfl_stage(T r[8], int m, bool keep_min) {
    #pragma unroll
    for (int e = 0; e < 8; e++) {
        T o = __shfl_xor_sync(0xffffffffu, r[e], m);
        r[e] = keep_min ? mn(r[e], o) : mx(r[e], o);
    }
}

// Merge-path: produce merged outputs [d, d+8) of merge(A[0..L), B[0..L)),
// both ascending. Binary-search the diagonal, load 8+8 windows (INF-padded),
// take lowest 8 via one min stage + bitonic-merge-8 ascending.
template <typename T>
static __device__ __forceinline__ void merge_lower8(
    const T* __restrict__ A, const T* __restrict__ B,
    int d, int L, T INFV, T out[8])
{
    int lo = (d > L) ? (d - L) : 0;
    int hi = (d < L) ? d : L;
    while (lo < hi) {
        int mid = (lo + hi) >> 1;
        if (A[mid] < B[d - 1 - mid]) lo = mid + 1;
        else                         hi = mid;
    }
    const int i = lo;
    const int j = d - lo;

    T Aw[8], Bw[8];
    #pragma unroll
    for (int r = 0; r < 8; r++) {
        int ia = (i + r < L) ? (i + r) : (L - 1);
        T  va = A[ia];
        Aw[r] = (i + r < L) ? va : INFV;
        int ib = (j + r < L) ? (j + r) : (L - 1);
        T  vb = B[ib];
        Bw[r] = (j + r < L) ? vb : INFV;
    }
    // lowest 8 of the 16 (Aw asc ++ reverse(Bw) desc is bitonic)
    #pragma unroll
    for (int r = 0; r < 8; r++) out[r] = mn(Aw[r], Bw[7 - r]);
    // sort the bitonic 8 ascending
    cea(out[0], out[4]); cea(out[1], out[5]); cea(out[2], out[6]); cea(out[3], out[7]);
    cea(out[0], out[2]); cea(out[1], out[3]); cea(out[4], out[6]); cea(out[5], out[7]);
    cea(out[0], out[1]); cea(out[2], out[3]); cea(out[4], out[5]); cea(out[6], out[7]);
}

__global__ __launch_bounds__(NT, 2)
void w1_row_kernel(const float4* __restrict__ pred,
                   const float4* __restrict__ tru)
{
    __shared__ __align__(16) float sa[N_COLS];
    __shared__ __align__(16) int   sb[N_COLS];
    __shared__ float red[16];

    const int row = blockIdx.x;
    const int t   = threadIdx.x;

    float a[8]; int b[8];
    {
        const size_t base = (size_t)row * (N_COLS / 4) + t * 2;
        float4 p0 = pred[base], p1 = pred[base + 1];
        float4 q0 = tru[base],  q1 = tru[base + 1];
        a[0]=p0.x; a[1]=p0.y; a[2]=p0.z; a[3]=p0.w;
        a[4]=p1.x; a[5]=p1.y; a[6]=p1.z; a[7]=p1.w;
        b[0]=__float_as_int(q0.x); b[1]=__float_as_int(q0.y);
        b[2]=__float_as_int(q0.z); b[3]=__float_as_int(q0.w);
        b[4]=__float_as_int(q1.x); b[5]=__float_as_int(q1.y);
        b[6]=__float_as_int(q1.z); b[7]=__float_as_int(q1.w);
    }

    // ---- Phase 1: bitonic to ascending runs of 256 (regs + shfl only) ----
    const bool up8 = ((t & 1) == 0);
    sort8(a, up8);
    sort8(b, up8);

    #pragma unroll
    for (int k = 16; k <= 128; k <<= 1) {
        const bool up = (((t << 3) & k) == 0);
        #pragma unroll
        for (int j = k >> 1; j >= 8; j >>= 1) {
            const int  m        = j >> 3;
            const bool keep_min = (((t & m) == 0) == up);
            shfl_stage(a, m, keep_min);
            shfl_stage(b, m, keep_min);
        }
        local_merge8(a, up);
        local_merge8(b, up);
    }
    // k = 256: force ascending everywhere (all 256-runs ascending)
    {
        #pragma unroll
        for (int j = 128; j >= 8; j >>= 1) {
            const int  m        = j >> 3;
            const bool keep_min = ((t & m) == 0);
            shfl_stage(a, m, keep_min);
            shfl_stage(b, m, keep_min);
        }
        local_merge8(a, true);
        local_merge8(b, true);
    }

    // canonical write: thread t owns elements [t*8, t*8+8)
    reinterpret_cast<float4*>(sa)[t * 2]     = make_float4(a[0], a[1], a[2], a[3]);
    reinterpret_cast<float4*>(sa)[t * 2 + 1] = make_float4(a[4], a[5], a[6], a[7]);
    reinterpret_cast<int4*>(sb)[t * 2]       = make_int4(b[0], b[1], b[2], b[3]);
    reinterpret_cast<int4*>(sb)[t * 2 + 1]   = make_int4(b[4], b[5], b[6], b[7]);
    __syncthreads();

    // ---- Phase 2: 4 merge-path passes 256 -> 4096 ----
    float ma[8]; int mb[8];
    #pragma unroll
    for (int p = 0; p < 4; p++) {
        const int L     = 256 << p;
        const int d0    = t * 8;
        const int base2 = d0 & ~(2 * L - 1);
        const int d     = d0 - base2;

        merge_lower8(sa + base2, sa + base2 + L, d, L,
                     __int_as_float(0x7f800000), ma);
        merge_lower8(sb + base2, sb + base2 + L, d, L,
                     0x7f800000, mb);
        __syncthreads();

        if (p < 3) {
            reinterpret_cast<float4*>(sa + d0)[0] = make_float4(ma[0], ma[1], ma[2], ma[3]);
            reinterpret_cast<float4*>(sa + d0)[1] = make_float4(ma[4], ma[5], ma[6], ma[7]);
            reinterpret_cast<int4*>(sb + d0)[0]   = make_int4(mb[0], mb[1], mb[2], mb[3]);
            reinterpret_cast<int4*>(sb + d0)[1]   = make_int4(mb[4], mb[5], mb[6], mb[7]);
            __syncthreads();
        }
    }

    // ---- |sorted diff| reduction; final octets live in registers ----
    float local = 0.0f;
    #pragma unroll
    for (int r = 0; r < 8; r++)
        local += fabsf(ma[r] - __int_as_float(mb[r]));

    #pragma unroll
    for (int o = 16; o > 0; o >>= 1)
        local += __shfl_down_sync(0xffffffffu, local, o);
    if ((t & 31) == 0) red[t >> 5] = local;
    __syncthreads();
    if (t < 32) {
        float v = (t < 16) ? red[t] : 0.0f;
        #pragma unroll
        for (int o = 8; o > 0; o >>= 1)
            v += __shfl_down_sync(0xffffffffu, v, o);
        if (t == 0) g_row_sums[row] = v;
    }
}

// Deterministic final reduction: single block, fixed iteration order.
__global__ void w1_reduce_kernel(float* __restrict__ out, int B)
{
    __shared__ float red[32];
    float local = 0.0f;
    for (int i = threadIdx.x; i < B; i += 1024)
        local += g_row_sums[i];
    #pragma unroll
    for (int o = 16; o > 0; o >>= 1)
        local += __shfl_down_sync(0xffffffffu, local, o);
    if ((threadIdx.x & 31) == 0) red[threadIdx.x >> 5] = local;
    __syncthreads();
    if (threadIdx.x < 32) {
        float v = red[threadIdx.x];
        #pragma unroll
        for (int o = 16; o > 0; o >>= 1)
            v += __shfl_down_sync(0xffffffffu, v, o);
        if (threadIdx.x == 0)
            out[0] = v / ((float)N_COLS * (float)B);
    }
}

extern "C" void kernel_launch(void* const* d_in, const int* in_sizes, int n_in,
                              void* d_out, int out_size)
{
    const float4* pred = (const float4*)d_in[0];
    const float4* tru  = (const float4*)d_in[1];
    float* out = (float*)d_out;

    const int B = in_sizes[0] / N_COLS;  // 4096

    w1_row_kernel<<<B, NT>>>(pred, tru);
    w1_reduce_kernel<<<1, 1024>>>(out, B);
}

// round 7
// speedup vs baseline: 3.7260x; 1.0134x over previous
#include <cuda_runtime.h>
#include <cuda_bf16.h>

#define N_COLS 4096
#define NT     512          // threads per row-CTA; 8 elements/thread/array

__device__ float g_row_sums[8192];

// float -> FMNMX (fma pipe), int -> IMNMX (alu pipe).
// Inputs are non-negative floats, so int bit-pattern order == float order.
static __device__ __forceinline__ float mn(float x, float y) { return fminf(x, y); }
static __device__ __forceinline__ float mx(float x, float y) { return fmaxf(x, y); }
static __device__ __forceinline__ int   mn(int x, int y)     { return ::min(x, y); }
static __device__ __forceinline__ int   mx(int x, int y)     { return ::max(x, y); }

template <typename T>
static __device__ __forceinline__ void ce(T& x, T& y, bool up) {
    T lo = mn(x, y);
    T hi = mx(x, y);
    x = up ? lo : hi;
    y = up ? hi : lo;
}
template <typename T>
static __device__ __forceinline__ void cea(T& x, T& y) {
    T lo = mn(x, y);
    y = mx(x, y);
    x = lo;
}

template <typename T>
static __device__ __forceinline__ void sort8(T r[8], bool up8) {
    ce(r[0], r[1], true );  ce(r[2], r[3], false);
    ce(r[4], r[5], true );  ce(r[6], r[7], false);
    ce(r[0], r[2], true );  ce(r[1], r[3], true );
    ce(r[4], r[6], false);  ce(r[5], r[7], false);
    ce(r[0], r[1], true );  ce(r[2], r[3], true );
    ce(r[4], r[5], false);  ce(r[6], r[7], false);
    ce(r[0], r[4], up8); ce(r[1], r[5], up8); ce(r[2], r[6], up8); ce(r[3], r[7], up8);
    ce(r[0], r[2], up8); ce(r[1], r[3], up8); ce(r[4], r[6], up8); ce(r[5], r[7], up8);
    ce(r[0], r[1], up8); ce(r[2], r[3], up8); ce(r[4], r[5], up8); ce(r[6], r[7], up8);
}

template <typename T>
static __device__ __forceinline__ void local_merge8(T r[8], bool up) {
    ce(r[0], r[4], up); ce(r[1], r[5], up); ce(r[2], r[6], up); ce(r[3], r[7], up);
    ce(r[0], r[2], up); ce(r[1], r[3], up); ce(r[4], r[6], up); ce(r[5], r[7], up);
    ce(r[0], r[1], up); ce(r[2], r[3], up); ce(r[4], r[5], up); ce(r[6], r[7], up);
}

template <typename T>
static __device__ __forceinline__ void shfl_stage(T r[8], int m, bool keep_min) {
    #pragma unroll
    for (int e = 0; e < 8; e++) {
        T o = __shfl_xor_sync(0xffffffffu, r[e], m);
        r[e] = keep_min ? mn(r[e], o) : mx(r[e], o);
    }
}

__global__ __launch_bounds__(NT, 2)
void w1_row_kernel(const float4* __restrict__ pred,
                   const float4* __restrict__ tru)
{
    // +8 padding so merge windows can read past the pair end unpredicated.
    __shared__ __align__(16) float sa[N_COLS + 8];
    __shared__ __align__(16) int   sb[N_COLS + 8];
    __shared__ float red[16];

    const int row = blockIdx.x;
    const int t   = threadIdx.x;

    float a[8]; int b[8];
    {
        const size_t base = (size_t)row * (N_COLS / 4) + t * 2;
        float4 p0 = pred[base], p1 = pred[base + 1];
        float4 q0 = tru[base],  q1 = tru[base + 1];
        a[0]=p0.x; a[1]=p0.y; a[2]=p0.z; a[3]=p0.w;
        a[4]=p1.x; a[5]=p1.y; a[6]=p1.z; a[7]=p1.w;
        b[0]=__float_as_int(q0.x); b[1]=__float_as_int(q0.y);
        b[2]=__float_as_int(q0.z); b[3]=__float_as_int(q0.w);
        b[4]=__float_as_int(q1.x); b[5]=__float_as_int(q1.y);
        b[6]=__float_as_int(q1.z); b[7]=__float_as_int(q1.w);
    }

    // ---- Phase 1: bitonic to ascending runs of 512 ----
    const bool up8 = ((t & 1) == 0);
    sort8(a, up8);
    sort8(b, up8);

    // k = 16..256, standard alternating directions
    #pragma unroll
    for (int k = 16; k <= 256; k <<= 1) {
        const bool up = (((t << 3) & k) == 0);
        #pragma unroll
        for (int j = k >> 1; j >= 8; j >>= 1) {
            const int  m        = j >> 3;
            const bool keep_min = (((t & m) == 0) == up);
            shfl_stage(a, m, keep_min);
            shfl_stage(b, m, keep_min);
        }
        local_merge8(a, up);
        local_merge8(b, up);
    }

    // k = 512, forced ascending. j=256 -> smem exchange (partner thread t^32).
    {
        #pragma unroll
        for (int e = 0; e < 8; e++) { sa[e * NT + t] = a[e]; sb[e * NT + t] = b[e]; }
        __syncthreads();
        const int  pt = t ^ 32;
        const bool km = ((t & 32) == 0);
        #pragma unroll
        for (int e = 0; e < 8; e++) {
            float oa = sa[e * NT + pt];
            int   ob = sb[e * NT + pt];
            a[e] = km ? mn(a[e], oa) : mx(a[e], oa);
            b[e] = km ? mn(b[e], ob) : mx(b[e], ob);
        }
        __syncthreads();
        // j = 128..8 via shfl, all-ascending
        #pragma unroll
        for (int m = 16; m >= 1; m >>= 1) {
            const bool keep_min = ((t & m) == 0);
            shfl_stage(a, m, keep_min);
            shfl_stage(b, m, keep_min);
        }
        local_merge8(a, true);
        local_merge8(b, true);
    }

    // canonical layout: thread t owns [t*8, t*8+8)
    reinterpret_cast<float4*>(sa)[t * 2]     = make_float4(a[0], a[1], a[2], a[3]);
    reinterpret_cast<float4*>(sa)[t * 2 + 1] = make_float4(a[4], a[5], a[6], a[7]);
    reinterpret_cast<int4*>(sb)[t * 2]       = make_int4(b[0], b[1], b[2], b[3]);
    reinterpret_cast<int4*>(sb)[t * 2 + 1]   = make_int4(b[4], b[5], b[6], b[7]);
    __syncthreads();

    // ---- Phase 2: 3 merge-path passes 512 -> 4096, fused dual search ----
    const float INFF = __int_as_float(0x7f800000);
    const int   INFI = 0x7f800000;

    float of[8]; int oi[8];
    #pragma unroll
    for (int p = 0; p < 3; p++) {
        const int L     = 512 << p;
        const int d0    = t * 8;
        const int base2 = d0 & ~(2 * L - 1);
        const int d     = d0 - base2;

        const float* __restrict__ Af = sa + base2;
        const float* __restrict__ Bf = Af + L;
        const int*   __restrict__ Ai = sb + base2;
        const int*   __restrict__ Bi = Ai + L;

        // dual binary search (interleaved for ILP on the dependent LDS chains)
        int lof = (d > L) ? (d - L) : 0;
        int hif = (d < L) ? d : L;
        int loi = lof, hii = hif;
        while ((lof < hif) | (loi < hii)) {
            if (lof < hif) {
                int m = (lof + hif) >> 1;
                if (Af[m] < Bf[d - 1 - m]) lof = m + 1; else hif = m;
            }
            if (loi < hii) {
                int m = (loi + hii) >> 1;
                if (Ai[m] < Bi[d - 1 - m]) loi = m + 1; else hii = m;
            }
        }

        // float array: window + lowest-8 + ascending sort of bitonic octet
        {
            const int i = lof, j = d - lof;
            float Aw[8], Bw[8];
            #pragma unroll
            for (int r = 0; r < 8; r++) Aw[r] = (i + r < L) ? Af[i + r] : INFF;
            #pragma unroll
            for (int r = 0; r < 8; r++) Bw[r] = (j + r < L) ? Bf[j + r] : INFF;
            #pragma unroll
            for (int r = 0; r < 8; r++) of[r] = mn(Aw[r], Bw[7 - r]);
            cea(of[0], of[4]); cea(of[1], of[5]); cea(of[2], of[6]); cea(of[3], of[7]);
            cea(of[0], of[2]); cea(of[1], of[3]); cea(of[4], of[6]); cea(of[5], of[7]);
            cea(of[0], of[1]); cea(of[2], of[3]); cea(of[4], of[5]); cea(of[6], of[7]);
        }
        // int array
        {
            const int i = loi, j = d - loi;
            int Aw[8], Bw[8];
            #pragma unroll
            for (int r = 0; r < 8; r++) Aw[r] = (i + r < L) ? Ai[i + r] : INFI;
            #pragma unroll
            for (int r = 0; r < 8; r++) Bw[r] = (j + r < L) ? Bi[j + r] : INFI;
            #pragma unroll
            for (int r = 0; r < 8; r++) oi[r] = mn(Aw[r], Bw[7 - r]);
            cea(oi[0], oi[4]); cea(oi[1], oi[5]); cea(oi[2], oi[6]); cea(oi[3], oi[7]);
            cea(oi[0], oi[2]); cea(oi[1], oi[3]); cea(oi[4], oi[6]); cea(oi[5], oi[7]);
            cea(oi[0], oi[1]); cea(oi[2], oi[3]); cea(oi[4], oi[5]); cea(oi[6], oi[7]);
        }
        __syncthreads();

        if (p < 2) {
            reinterpret_cast<float4*>(sa)[t * 2]     = make_float4(of[0], of[1], of[2], of[3]);
            reinterpret_cast<float4*>(sa)[t * 2 + 1] = make_float4(of[4], of[5], of[6], of[7]);
            reinterpret_cast<int4*>(sb)[t * 2]       = make_int4(oi[0], oi[1], oi[2], oi[3]);
            reinterpret_cast<int4*>(sb)[t * 2 + 1]   = make_int4(oi[4], oi[5], oi[6], oi[7]);
            __syncthreads();
        }
    }

    // ---- |sorted diff| reduction; final octets in registers ----
    float local = 0.0f;
    #pragma unroll
    for (int r = 0; r < 8; r++)
        local += fabsf(of[r] - __int_as_float(oi[r]));

    #pragma unroll
    for (int o = 16; o > 0; o >>= 1)
        local += __shfl_down_sync(0xffffffffu, local, o);
    if ((t & 31) == 0) red[t >> 5] = local;
    __syncthreads();
    if (t < 32) {
        float v = (t < 16) ? red[t] : 0.0f;
        #pragma unroll
        for (int o = 8; o > 0; o >>= 1)
            v += __shfl_down_sync(0xffffffffu, v, o);
        if (t == 0) g_row_sums[row] = v;
    }
}

// Deterministic final reduction: single block, fixed iteration order.
__global__ void w1_reduce_kernel(float* __restrict__ out, int B)
{
    __shared__ float red[32];
    float local = 0.0f;
    for (int i = threadIdx.x; i < B; i += 1024)
        local += g_row_sums[i];
    #pragma unroll
    for (int o = 16; o > 0; o >>= 1)
        local += __shfl_down_sync(0xffffffffu, local, o);
    if ((threadIdx.x & 31) == 0) red[threadIdx.x >> 5] = local;
    __syncthreads();
    if (threadIdx.x < 32) {
        float v = red[threadIdx.x];
        #pragma unroll
        for (int o = 16; o > 0; o >>= 1)
            v += __shfl_down_sync(0xffffffffu, v, o);
        if (threadIdx.x == 0)
            out[0] = v / ((float)N_COLS * (float)B);
    }
}

extern "C" void kernel_launch(void* const* d_in, const int* in_sizes, int n_in,
                              void* d_out, int out_size)
{
    const float4* pred = (const float4*)d_in[0];
    const float4* tru  = (const float4*)d_in[1];
    float* out = (float*)d_out;

    const int B = in_sizes[0] / N_COLS;  // 4096

    w1_row_kernel<<<B, NT>>>(pred, tru);
    w1_reduce_kernel<<<1, 1024>>>(out, B);
}